// round 16
// baseline (speedup 1.0000x reference)
#include <cuda_runtime.h>
#include <math.h>
#include <stdint.h>

#define VOCAB 32000
#define EMB 256
#define HID 256
#define BATCH 64
#define SEQT 2048

// Scratch: V[v][j] = sum_e emb[v][e]*W_ih[e][j] + b_ih[j] + b_hh[j]  (32 MB, L2-resident)
__device__ float g_V[VOCAB * HID];

// ---------------------------------------------------------------------------
// f32x2 packed helpers (PTX-only; ptxas won't auto-fuse)
// ---------------------------------------------------------------------------
__device__ __forceinline__ unsigned long long pack2(float lo, float hi) {
    unsigned long long r;
    asm("mov.b64 %0, {%1, %2};" : "=l"(r) : "f"(lo), "f"(hi));
    return r;
}
__device__ __forceinline__ void fma2(unsigned long long& acc,
                                     unsigned long long a, unsigned long long b) {
    asm("fma.rn.f32x2 %0, %1, %2, %0;" : "+l"(acc) : "l"(a), "l"(b));
}
__device__ __forceinline__ unsigned long long add2(unsigned long long a,
                                                   unsigned long long b) {
    unsigned long long r;
    asm("add.rn.f32x2 %0, %1, %2;" : "=l"(r) : "l"(a), "l"(b));
    return r;
}
__device__ __forceinline__ void unpack2(unsigned long long v, float& lo, float& hi) {
    asm("mov.b64 {%0, %1}, %2;" : "=f"(lo), "=f"(hi) : "l"(v));
}

// Cluster / mbarrier helpers
__device__ __forceinline__ uint32_t smem_u32(const void* p) {
    uint32_t a;
    asm("{ .reg .u64 t; cvta.to.shared.u64 t, %1; cvt.u32.u64 %0, t; }"
        : "=r"(a) : "l"(p));
    return a;
}
__device__ __forceinline__ uint32_t mapa_peer(uint32_t addr, uint32_t rank) {
    uint32_t r;
    asm("mapa.shared::cluster.u32 %0, %1, %2;" : "=r"(r) : "r"(addr), "r"(rank));
    return r;
}
__device__ __forceinline__ void mbar_init(uint32_t addr, uint32_t count) {
    asm volatile("mbarrier.init.shared.b64 [%0], %1;" :: "r"(addr), "r"(count) : "memory");
}
__device__ __forceinline__ void mbar_expect_tx(uint32_t addr, uint32_t bytes) {
    asm volatile("mbarrier.arrive.expect_tx.shared.b64 _, [%0], %1;"
                 :: "r"(addr), "r"(bytes) : "memory");
}
// Remote b64 store fused with peer-mbar tx completion (2 h values / message)
__device__ __forceinline__ void st_async_b64(uint32_t remote_addr,
                                             unsigned long long v,
                                             uint32_t remote_mbar) {
    asm volatile(
        "st.async.shared::cluster.mbarrier::complete_tx::bytes.b64 [%0], %1, [%2];"
        :: "r"(remote_addr), "l"(v), "r"(remote_mbar) : "memory");
}
__device__ __forceinline__ void mbar_wait_parity(uint32_t addr, uint32_t parity) {
    uint32_t done;
    asm volatile(
        "{\n\t"
        ".reg .pred p;\n\t"
        "mbarrier.try_wait.parity.acquire.cluster.shared::cta.b64 p, [%1], %2;\n\t"
        "selp.b32 %0, 1, 0, p;\n\t"
        "}" : "=r"(done) : "r"(addr), "r"(parity) : "memory");
    if (!done) {
        asm volatile(
            "{\n\t"
            ".reg .pred P1;\n\t"
            "WL_%=:\n\t"
            "mbarrier.try_wait.parity.acquire.cluster.shared::cta.b64 P1, [%0], %1, 0x989680;\n\t"
            "@P1 bra.uni WD_%=;\n\t"
            "bra.uni WL_%=;\n\t"
            "WD_%=:\n\t"
            "}" :: "r"(addr), "r"(parity) : "memory");
    }
}
#define CLUSTER_SYNC() do { \
    asm volatile("barrier.cluster.arrive.aligned;" ::: "memory"); \
    asm volatile("barrier.cluster.wait.aligned;" ::: "memory"); \
} while (0)

// ---------------------------------------------------------------------------
// Kernel 1: vocab projection GEMM  [32000,256] x [256,256] + bias  (f32x2)
// ---------------------------------------------------------------------------
__global__ void __launch_bounds__(256) vocab_proj_kernel(
    const float* __restrict__ emb, const float* __restrict__ W_ih,
    const float* __restrict__ b_ih, const float* __restrict__ b_hh)
{
    __shared__ float As_T[32][68];
    const int row0 = blockIdx.x * 64;
    const int j = threadIdx.x;

    const float bias = b_ih[j] + b_hh[j];

    unsigned long long acc[32];
#pragma unroll
    for (int p = 0; p < 32; p++) acc[p] = 0ull;

#pragma unroll 1
    for (int k0 = 0; k0 < EMB; k0 += 32) {
        __syncthreads();
#pragma unroll
        for (int it = 0; it < 8; it++) {
            int idx = it * 256 + threadIdx.x;
            int r  = idx >> 5;
            int kk = idx & 31;
            As_T[kk][r] = emb[(size_t)(row0 + r) * EMB + (k0 + kk)];
        }
        __syncthreads();

        float wt[32];
#pragma unroll
        for (int kk = 0; kk < 32; kk++)
            wt[kk] = W_ih[(size_t)(k0 + kk) * HID + j];

#pragma unroll
        for (int kk = 0; kk < 32; kk++) {
            unsigned long long ws = pack2(wt[kk], wt[kk]);
#pragma unroll
            for (int rp2 = 0; rp2 < 16; rp2++) {
                ulonglong2 av = *(const ulonglong2*)&As_T[kk][4 * rp2];
                fma2(acc[2 * rp2 + 0], av.x, ws);
                fma2(acc[2 * rp2 + 1], av.y, ws);
            }
        }
    }

#pragma unroll
    for (int p = 0; p < 32; p++) {
        float lo, hi;
        unpack2(acc[p], lo, hi);
        g_V[(size_t)(row0 + 2 * p + 0) * HID + j] = lo + bias;
        g_V[(size_t)(row0 + 2 * p + 1) * HID + j] = hi + bias;
    }
}

// ---------------------------------------------------------------------------
// Kernel 2: recurrence. 2-CTA cluster per chain, two-phase all-warp FMA.
// Thread t: col = t&127, sub = t>>7 (k-quarter within each half).
//   Phase L (before wait, during peer transit): k in [rank*128+sub*64, +64).
//   Phase R (after mbar arrival):               k in [peer*128+sub*64, +64).
// Each phase = 32 fma2/thread -> 128 port cyc (vs 256 in R14's remote path).
// Merge: t>=128 STS partial -> bar#1 (arrive/sync split) -> t<128 finalize:
// tanh, store h local, pack pairs via shfl, 64 x st.async.b64 to peer.
// bar#2 (full) orders h stores before next phase L.
// ---------------------------------------------------------------------------
__global__ void __launch_bounds__(256, 1) __cluster_dims__(2, 1, 1)
rnn_kernel(const int* __restrict__ source, const float* __restrict__ W_hh,
           float* __restrict__ out)
{
    __shared__ __align__(16) float hs[2][256];
    __shared__ float partial[128];
    __shared__ int   src_s[SEQT];
    __shared__ __align__(8) unsigned long long mbar[2];

    const int t   = threadIdx.x;
    const int l   = t & 31;
    const int col = t & 127;
    const int sub = t >> 7;
    const int b   = blockIdx.x >> 1;

    uint32_t rank;
    asm("mov.u32 %0, %%cluster_ctarank;" : "=r"(rank));

    const int jout = (int)rank * 128 + col;          // this CTA's output column
    const int kbL  = (int)rank * 128 + sub * 64;     // local k-quarter base
    const int kbR  = ((int)rank ^ 1) * 128 + sub * 64;  // peer k-quarter base

    for (int i = t; i < SEQT; i += 256) src_s[i] = source[b * SEQT + i];

    // W slices register-resident: 32 f32x2 per phase (64 total = 128 regs)
    unsigned long long wL[32], wR[32];
#pragma unroll
    for (int i = 0; i < 32; i++) {
        wL[i] = pack2(W_hh[(size_t)(kbL + 2 * i + 0) * HID + jout],
                      W_hh[(size_t)(kbL + 2 * i + 1) * HID + jout]);
        wR[i] = pack2(W_hh[(size_t)(kbR + 2 * i + 0) * HID + jout],
                      W_hh[(size_t)(kbR + 2 * i + 1) * HID + jout]);
    }

    hs[0][t] = 0.0f;
    hs[1][t] = 0.0f;
    if (t == 0) {
        mbar_init(smem_u32(&mbar[0]), 1);
        mbar_init(smem_u32(&mbar[1]), 1);
        mbar_expect_tx(smem_u32(&mbar[0]), 512);  // pre-arm phase 0 of both
        mbar_expect_tx(smem_u32(&mbar[1]), 512);
    }

    // Sender targets: even cols send a b64 covering (col, col+1)
    uint32_t peer_h64[2], peer_mbar[2], mbar_local[2];
    {
        const int jev = (int)rank * 128 + (col & ~1);
        peer_h64[0]  = mapa_peer(smem_u32(&hs[0][jev]), rank ^ 1u);
        peer_h64[1]  = mapa_peer(smem_u32(&hs[1][jev]), rank ^ 1u);
        peer_mbar[0] = mapa_peer(smem_u32(&mbar[0]), rank ^ 1u);
        peer_mbar[1] = mapa_peer(smem_u32(&mbar[1]), rank ^ 1u);
        mbar_local[0] = smem_u32(&mbar[0]);
        mbar_local[1] = smem_u32(&mbar[1]);
    }

    __syncthreads();
    CLUSTER_SYNC();  // mbar init + expect_tx + zeroed hs visible cluster-wide

    float hval = 0.0f;

#pragma unroll 1
    for (int step = 0; step < SEQT; step++) {
        const int cur = step & 1;
        const int nxt = cur ^ 1;

        // Prefetch x-projection (finalizers only); in flight through phase L +
        // wait + phase R.
        float xv = 0.0f;
        if (t < 128) xv = g_V[(size_t)src_s[step] * HID + jout];

        unsigned long long a0 = 0, a1 = 0, a2 = 0, a3 = 0;
        unsigned long long b0 = 0, b1 = 0, b2 = 0, b3 = 0;

        // ---- Phase L: local k-quarter (h produced locally last step) ----
        {
            const ulonglong2* hp2 = (const ulonglong2*)(&hs[cur][kbL]);
#pragma unroll
            for (int q = 0; q < 16; q += 4) {
                ulonglong2 h0 = hp2[q + 0];
                ulonglong2 h1 = hp2[q + 1];
                ulonglong2 h2 = hp2[q + 2];
                ulonglong2 h3 = hp2[q + 3];
                fma2(a0, h0.x, wL[2 * q + 0]); fma2(b0, h0.y, wL[2 * q + 1]);
                fma2(a1, h1.x, wL[2 * q + 2]); fma2(b1, h1.y, wL[2 * q + 3]);
                fma2(a2, h2.x, wL[2 * q + 4]); fma2(b2, h2.y, wL[2 * q + 5]);
                fma2(a3, h3.x, wL[2 * q + 6]); fma2(b3, h3.y, wL[2 * q + 7]);
            }
        }

        // ---- Wait for the peer's h half (sent one step ago) ----
        if (step > 0) {
            mbar_wait_parity(mbar_local[cur], ((uint32_t)(step - 1) >> 1) & 1u);
            if (t == 0) mbar_expect_tx(mbar_local[cur], 512);  // re-arm next phase
        }

        // ---- Phase R: peer k-quarter ----
        {
            const ulonglong2* hp2 = (const ulonglong2*)(&hs[cur][kbR]);
#pragma unroll
            for (int q = 0; q < 16; q += 4) {
                ulonglong2 h0 = hp2[q + 0];
                ulonglong2 h1 = hp2[q + 1];
                ulonglong2 h2 = hp2[q + 2];
                ulonglong2 h3 = hp2[q + 3];
                fma2(a0, h0.x, wR[2 * q + 0]); fma2(b0, h0.y, wR[2 * q + 1]);
                fma2(a1, h1.x, wR[2 * q + 2]); fma2(b1, h1.y, wR[2 * q + 3]);
                fma2(a2, h2.x, wR[2 * q + 4]); fma2(b2, h2.y, wR[2 * q + 5]);
                fma2(a3, h3.x, wR[2 * q + 6]); fma2(b3, h3.y, wR[2 * q + 7]);
            }
        }

        unsigned long long s = add2(add2(add2(a0, a1), add2(a2, a3)),
                                    add2(add2(b0, b1), add2(b2, b3)));
        float lo, hi;
        unpack2(s, lo, hi);
        const float pr = lo + hi;

        // ---- Merge across the two k-quarters of each column ----
        if (t >= 128) {
            partial[col] = pr;
            asm volatile("bar.arrive 1, 256;" ::: "memory");  // non-blocking
        } else {
            asm volatile("bar.sync 1, 256;" ::: "memory");    // partner STS in

            const float pre = xv + pr + partial[col];
            const float e = __expf(2.0f * pre);
            hval = 1.0f - __fdividef(2.0f, e + 1.0f);

            hs[nxt][jout] = hval;                              // local copy

            // Pack (even, odd) column pair; even lanes send ONE b64 message
            const float hnext = __shfl_down_sync(0xffffffffu, hval, 1);
            if ((l & 1) == 0)
                st_async_b64(peer_h64[nxt], pack2(hval, hnext), peer_mbar[nxt]);
        }

        __syncthreads();  // h(nxt) local stores visible before next phase L
    }

    if (t < 128) out[b * HID + jout] = hval;

    CLUSTER_SYNC();  // keep peer SMEM alive for in-flight final st.asyncs
}

// ---------------------------------------------------------------------------
extern "C" void kernel_launch(void* const* d_in, const int* in_sizes, int n_in,
                              void* d_out, int out_size)
{
    const int*   source    = (const int*)d_in[0];
    const float* embedding = (const float*)d_in[1];
    const float* W_ih      = (const float*)d_in[2];
    const float* W_hh      = (const float*)d_in[3];
    const float* b_ih      = (const float*)d_in[4];
    const float* b_hh      = (const float*)d_in[5];
    float* out = (float*)d_out;

    vocab_proj_kernel<<<VOCAB / 64, 256>>>(embedding, W_ih, b_ih, b_hh);
    rnn_kernel<<<BATCH * 2, 256>>>(source, W_hh, out);
}

// round 17
// speedup vs baseline: 1.1545x; 1.1545x over previous
#include <cuda_runtime.h>
#include <math.h>
#include <stdint.h>

#define VOCAB 32000
#define EMB 256
#define HID 256
#define BATCH 64
#define SEQT 2048

// Scratch: V[v][j] = sum_e emb[v][e]*W_ih[e][j] + b_ih[j] + b_hh[j]  (32 MB, L2-resident)
__device__ float g_V[VOCAB * HID];

// ---------------------------------------------------------------------------
// f32x2 packed helpers (PTX-only; ptxas won't auto-fuse)
// ---------------------------------------------------------------------------
__device__ __forceinline__ unsigned long long pack2(float lo, float hi) {
    unsigned long long r;
    asm("mov.b64 %0, {%1, %2};" : "=l"(r) : "f"(lo), "f"(hi));
    return r;
}
__device__ __forceinline__ void fma2(unsigned long long& acc,
                                     unsigned long long a, unsigned long long b) {
    asm("fma.rn.f32x2 %0, %1, %2, %0;" : "+l"(acc) : "l"(a), "l"(b));
}
__device__ __forceinline__ unsigned long long add2(unsigned long long a,
                                                   unsigned long long b) {
    unsigned long long r;
    asm("add.rn.f32x2 %0, %1, %2;" : "=l"(r) : "l"(a), "l"(b));
    return r;
}
__device__ __forceinline__ void unpack2(unsigned long long v, float& lo, float& hi) {
    asm("mov.b64 {%0, %1}, %2;" : "=f"(lo), "=f"(hi) : "l"(v));
}

// Cluster / mbarrier helpers
__device__ __forceinline__ uint32_t smem_u32(const void* p) {
    uint32_t a;
    asm("{ .reg .u64 t; cvta.to.shared.u64 t, %1; cvt.u32.u64 %0, t; }"
        : "=r"(a) : "l"(p));
    return a;
}
__device__ __forceinline__ uint32_t mapa_peer(uint32_t addr, uint32_t rank) {
    uint32_t r;
    asm("mapa.shared::cluster.u32 %0, %1, %2;" : "=r"(r) : "r"(addr), "r"(rank));
    return r;
}
__device__ __forceinline__ void mbar_init(uint32_t addr, uint32_t count) {
    asm volatile("mbarrier.init.shared.b64 [%0], %1;" :: "r"(addr), "r"(count) : "memory");
}
__device__ __forceinline__ void mbar_expect_tx(uint32_t addr, uint32_t bytes) {
    asm volatile("mbarrier.arrive.expect_tx.shared.b64 _, [%0], %1;"
                 :: "r"(addr), "r"(bytes) : "memory");
}
// Remote store fused with peer-mbar tx completion (data + signal in one op)
__device__ __forceinline__ void st_async_f32(uint32_t remote_addr, float v,
                                             uint32_t remote_mbar) {
    asm volatile(
        "st.async.shared::cluster.mbarrier::complete_tx::bytes.b32 [%0], %1, [%2];"
        :: "r"(remote_addr), "r"(__float_as_int(v)), "r"(remote_mbar) : "memory");
}
__device__ __forceinline__ void mbar_wait_parity(uint32_t addr, uint32_t parity) {
    uint32_t done;
    asm volatile(
        "{\n\t"
        ".reg .pred p;\n\t"
        "mbarrier.try_wait.parity.acquire.cluster.shared::cta.b64 p, [%1], %2;\n\t"
        "selp.b32 %0, 1, 0, p;\n\t"
        "}" : "=r"(done) : "r"(addr), "r"(parity) : "memory");
    if (!done) {
        asm volatile(
            "{\n\t"
            ".reg .pred P1;\n\t"
            "WL_%=:\n\t"
            "mbarrier.try_wait.parity.acquire.cluster.shared::cta.b64 P1, [%0], %1, 0x989680;\n\t"
            "@P1 bra.uni WD_%=;\n\t"
            "bra.uni WL_%=;\n\t"
            "WD_%=:\n\t"
            "}" :: "r"(addr), "r"(parity) : "memory");
    }
}
#define CLUSTER_SYNC() do { \
    asm volatile("barrier.cluster.arrive.aligned;" ::: "memory"); \
    asm volatile("barrier.cluster.wait.aligned;" ::: "memory"); \
} while (0)

// ---------------------------------------------------------------------------
// Kernel 1: vocab projection GEMM  [32000,256] x [256,256] + bias  (f32x2)
// ---------------------------------------------------------------------------
__global__ void __launch_bounds__(256) vocab_proj_kernel(
    const float* __restrict__ emb, const float* __restrict__ W_ih,
    const float* __restrict__ b_ih, const float* __restrict__ b_hh)
{
    __shared__ float As_T[32][68];
    const int row0 = blockIdx.x * 64;
    const int j = threadIdx.x;

    const float bias = b_ih[j] + b_hh[j];

    unsigned long long acc[32];
#pragma unroll
    for (int p = 0; p < 32; p++) acc[p] = 0ull;

#pragma unroll 1
    for (int k0 = 0; k0 < EMB; k0 += 32) {
        __syncthreads();
#pragma unroll
        for (int it = 0; it < 8; it++) {
            int idx = it * 256 + threadIdx.x;
            int r  = idx >> 5;
            int kk = idx & 31;
            As_T[kk][r] = emb[(size_t)(row0 + r) * EMB + (k0 + kk)];
        }
        __syncthreads();

        float wt[32];
#pragma unroll
        for (int kk = 0; kk < 32; kk++)
            wt[kk] = W_ih[(size_t)(k0 + kk) * HID + j];

#pragma unroll
        for (int kk = 0; kk < 32; kk++) {
            unsigned long long ws = pack2(wt[kk], wt[kk]);
#pragma unroll
            for (int rp2 = 0; rp2 < 16; rp2++) {
                ulonglong2 av = *(const ulonglong2*)&As_T[kk][4 * rp2];
                fma2(acc[2 * rp2 + 0], av.x, ws);
                fma2(acc[2 * rp2 + 1], av.y, ws);
            }
        }
    }

#pragma unroll
    for (int p = 0; p < 32; p++) {
        float lo, hi;
        unpack2(acc[p], lo, hi);
        g_V[(size_t)(row0 + 2 * p + 0) * HID + j] = lo + bias;
        g_V[(size_t)(row0 + 2 * p + 1) * HID + j] = hi + bias;
    }
}

// ---------------------------------------------------------------------------
// Kernel 2: recurrence. 2-CTA cluster per chain (R14 engine, trimmed tail).
// Warp w: pair p = w&3 (cols p*32..p*32+31, one col/lane), kh = w>>2.
//  local warp  (kh == rank):   loads xv, FMA over own-produced h half,
//      partial[col] = pr + xv -> bar.arrive(pair), bar.sync(end).
//  remote warp (kh == rank^1): wait mbar -> FMA over peer h half ->
//      bar.sync(pair) [local pre-arrived] -> LDS partial, tanh, STS h local +
//      st.async h+signal to peer -> re-arm mbar (off critical path) ->
//      bar.arrive(end) -> straight into next step's wait.
// ---------------------------------------------------------------------------
__global__ void __launch_bounds__(256, 1) __cluster_dims__(2, 1, 1)
rnn_kernel(const int* __restrict__ source, const float* __restrict__ W_hh,
           float* __restrict__ out)
{
    __shared__ float hs[2][256];
    __shared__ float partial[128];
    __shared__ int   src_s[SEQT];
    __shared__ __align__(8) unsigned long long mbar[2];

    const int t  = threadIdx.x;
    const int w  = t >> 5;
    const int l  = t & 31;
    const int p  = w & 3;         // pair id
    const int kh = w >> 2;        // k-half this warp multiplies
    const int col = p * 32 + l;   // local output column 0..127
    const int k0  = kh * 128;
    const int b   = blockIdx.x >> 1;

    uint32_t rank;
    asm("mov.u32 %0, %%cluster_ctarank;" : "=r"(rank));

    const int  jout      = (int)rank * 128 + col;   // global output column
    const bool is_remote = (kh != (int)rank);       // warp-uniform

    for (int i = t; i < SEQT; i += 256) src_s[i] = source[b * SEQT + i];

    // W_hh[k0..k0+127][jout] register-resident as 64 f32x2
    unsigned long long wreg[64];
#pragma unroll
    for (int i = 0; i < 64; i++)
        wreg[i] = pack2(W_hh[(size_t)(k0 + 2 * i + 0) * HID + jout],
                        W_hh[(size_t)(k0 + 2 * i + 1) * HID + jout]);

    hs[0][t] = 0.0f;
    hs[1][t] = 0.0f;
    if (t == 0) {
        mbar_init(smem_u32(&mbar[0]), 1);
        mbar_init(smem_u32(&mbar[1]), 1);
        mbar_expect_tx(smem_u32(&mbar[0]), 512);  // pre-arm phase 0 of both
        mbar_expect_tx(smem_u32(&mbar[1]), 512);
    }

    // Peer addresses
    uint32_t peer_h[2], peer_mbar[2], mbar_local[2];
    peer_h[0]    = mapa_peer(smem_u32(&hs[0][jout]), rank ^ 1u);
    peer_h[1]    = mapa_peer(smem_u32(&hs[1][jout]), rank ^ 1u);
    peer_mbar[0] = mapa_peer(smem_u32(&mbar[0]), rank ^ 1u);
    peer_mbar[1] = mapa_peer(smem_u32(&mbar[1]), rank ^ 1u);
    mbar_local[0] = smem_u32(&mbar[0]);
    mbar_local[1] = smem_u32(&mbar[1]);

    __syncthreads();
    CLUSTER_SYNC();  // mbar init + expect visible cluster-wide before any st.async

    float hval = 0.0f;

#pragma unroll 1
    for (int step = 0; step < SEQT; step++) {
        const int cur = step & 1;
        const int nxt = cur ^ 1;

        if (is_remote) {
            if (step > 0)
                mbar_wait_parity(mbar_local[cur], ((uint32_t)(step - 1) >> 1) & 1u);

            const float* hp = &hs[cur][k0];   // peer half, mbar-gated
            unsigned long long a0 = 0, a1 = 0, a2 = 0, a3 = 0;
            unsigned long long b0 = 0, b1 = 0, b2 = 0, b3 = 0;
#pragma unroll
            for (int q = 0; q < 32; q += 4) {
                ulonglong2 h0 = *(const ulonglong2*)(hp + 4 * (q + 0));
                ulonglong2 h1 = *(const ulonglong2*)(hp + 4 * (q + 1));
                ulonglong2 h2 = *(const ulonglong2*)(hp + 4 * (q + 2));
                ulonglong2 h3 = *(const ulonglong2*)(hp + 4 * (q + 3));
                fma2(a0, h0.x, wreg[2 * q + 0]); fma2(b0, h0.y, wreg[2 * q + 1]);
                fma2(a1, h1.x, wreg[2 * q + 2]); fma2(b1, h1.y, wreg[2 * q + 3]);
                fma2(a2, h2.x, wreg[2 * q + 4]); fma2(b2, h2.y, wreg[2 * q + 5]);
                fma2(a3, h3.x, wreg[2 * q + 6]); fma2(b3, h3.y, wreg[2 * q + 7]);
            }
            unsigned long long s = add2(add2(add2(a0, a1), add2(a2, a3)),
                                        add2(add2(b0, b1), add2(b2, b3)));
            float lo, hi;
            unpack2(s, lo, hi);
            float pr = lo + hi;

            // Pair merge: local warp pre-arrived ~500cyc ago -> near-zero wait
            asm volatile("bar.sync %0, 64;" :: "r"(p + 1) : "memory");

            // partial[col] already includes xv (folded by local warp)
            float pre = pr + partial[col];
            float e = __expf(2.0f * pre);
            hval = 1.0f - __fdividef(2.0f, e + 1.0f);

            hs[nxt][jout] = hval;                 // local copy (for local warps)
            st_async_f32(peer_h[nxt], hval, peer_mbar[nxt]);  // data+signal fused

            // Re-arm this mbar's next phase AFTER the send (off critical path;
            // peer's next tx to it arrives a full period later)
            if (step > 0 && p == 0 && l == 0)
                mbar_expect_tx(mbar_local[cur], 512);

            // Non-blocking end-of-step: fall straight into next mbar wait
            asm volatile("bar.arrive 7, 256;" ::: "memory");
        } else {
            // Local warps own the xv gather (transit slack absorbs the LDG)
            float xv = g_V[(size_t)src_s[step] * HID + jout];

            const float* hp = &hs[cur][k0];   // own half, ordered by end-bar
            unsigned long long a0 = 0, a1 = 0, a2 = 0, a3 = 0;
            unsigned long long b0 = 0, b1 = 0, b2 = 0, b3 = 0;
#pragma unroll
            for (int q = 0; q < 32; q += 4) {
                ulonglong2 h0 = *(const ulonglong2*)(hp + 4 * (q + 0));
                ulonglong2 h1 = *(const ulonglong2*)(hp + 4 * (q + 1));
                ulonglong2 h2 = *(const ulonglong2*)(hp + 4 * (q + 2));
                ulonglong2 h3 = *(const ulonglong2*)(hp + 4 * (q + 3));
                fma2(a0, h0.x, wreg[2 * q + 0]); fma2(b0, h0.y, wreg[2 * q + 1]);
                fma2(a1, h1.x, wreg[2 * q + 2]); fma2(b1, h1.y, wreg[2 * q + 3]);
                fma2(a2, h2.x, wreg[2 * q + 4]); fma2(b2, h2.y, wreg[2 * q + 5]);
                fma2(a3, h3.x, wreg[2 * q + 6]); fma2(b3, h3.y, wreg[2 * q + 7]);
            }
            unsigned long long s = add2(add2(add2(a0, a1), add2(a2, a3)),
                                        add2(add2(b0, b1), add2(b2, b3)));
            float lo, hi;
            unpack2(s, lo, hi);
            partial[col] = lo + hi + xv;   // xv folded off the critical path

            // Publish partial early (non-blocking), then wait for finalizers:
            // release of bar 7 orders finalizer hs[nxt] writes (and their
            // partial[] reads) before our next-step hs read / partial write.
            asm volatile("bar.arrive %0, 64;" :: "r"(p + 1) : "memory");
            asm volatile("bar.sync 7, 256;" ::: "memory");
        }
    }

    if (is_remote) out[b * HID + jout] = hval;

    CLUSTER_SYNC();  // keep peer SMEM alive for in-flight final st.asyncs
}

// ---------------------------------------------------------------------------
extern "C" void kernel_launch(void* const* d_in, const int* in_sizes, int n_in,
                              void* d_out, int out_size)
{
    const int*   source    = (const int*)d_in[0];
    const float* embedding = (const float*)d_in[1];
    const float* W_ih      = (const float*)d_in[2];
    const float* W_hh      = (const float*)d_in[3];
    const float* b_ih      = (const float*)d_in[4];
    const float* b_hh      = (const float*)d_in[5];
    float* out = (float*)d_out;

    vocab_proj_kernel<<<VOCAB / 64, 256>>>(embedding, W_ih, b_ih, b_hh);
    rnn_kernel<<<BATCH * 2, 256>>>(source, W_hh, out);
}